// round 8
// baseline (speedup 1.0000x reference)
#include <cuda_runtime.h>
#include <cuda_bf16.h>

// Problem: out[b,c,t] = W[c, idx[b,t]] + bias[c]
//   idx: (256, 1, 2048) int32   [d_in[0]]
//   W:   (128, 32000)   fp32    [d_in[1]]
//   b:   (128,)         fp32    [d_in[2]]
//   out: (256, 128, 2048) fp32  = 256 MB
//
// Strategy:
//   K1: transpose+permute W into WT (V x 128), bias folded in.
//       WT float4 chunk k of row v = { W[k][v]+b[k], W[32+k][v]+b[32+k],
//                                      W[64+k][v]+b[64+k], W[96+k][v]+b[96+k] }
//       Channel permutation makes the SMEM scatter in K2 bank-conflict-free.
//   K2: per block: 64 tokens. Gather 64 x 512B contiguous rows from WT (L2-resident,
//       16.4MB), transpose in SMEM, write coalesced float4 along t with __stcs
//       (streaming: keep WT in L2).

#define BB  256
#define TT  2048
#define VV  32000
#define CC  128
#define TOK 64
#define TSTRIDE 65   // odd -> conflict-free scatter

__device__ float g_WT[(size_t)VV * CC];

// ---------------- K1: transpose + channel-permute + bias fold ----------------
// grid = V/32 blocks, 256 threads. Each block: all 128 channels x 32 vocab cols.
__global__ void __launch_bounds__(256, 6)
wt_build_kernel(const float* __restrict__ W, const float* __restrict__ bias) {
    __shared__ float sm[CC][33];           // [c][v_local], +1 pad
    const int v0 = blockIdx.x * 32;
    const int tid = threadIdx.x;
    const int vl = tid & 31;
    const int cw = tid >> 5;               // warp id -> c group

    // load: coalesced along v, conflict-free smem store (consecutive vl)
    #pragma unroll
    for (int it = 0; it < 16; ++it) {
        int c = it * 8 + cw;
        sm[c][vl] = W[(size_t)c * VV + v0 + vl];
    }
    __syncthreads();

    float4* WT4 = reinterpret_cast<float4*>(g_WT);
    #pragma unroll
    for (int it = 0; it < 4; ++it) {
        int li   = it * 256 + tid;
        int vloc = li >> 5;                // 0..31, constant per warp
        int k    = li & 31;                // lane
        float4 f;
        // smem read banks: ((k+32m)*33 + vloc) % 32 = (k + vloc) % 32 -> distinct
        f.x = sm[k     ][vloc] + __ldg(&bias[k     ]);
        f.y = sm[k + 32][vloc] + __ldg(&bias[k + 32]);
        f.z = sm[k + 64][vloc] + __ldg(&bias[k + 64]);
        f.w = sm[k + 96][vloc] + __ldg(&bias[k + 96]);
        WT4[(size_t)(v0 + vloc) * 32 + k] = f;   // 512B coalesced per warp
    }
}

// ---------------- K2: gather + transpose + streamed store ----------------
// grid = (T/TOK, B), 256 threads.
__global__ void __launch_bounds__(256, 4)
gather_kernel(const int* __restrict__ idx, float* __restrict__ out) {
    __shared__ float tile[CC * TSTRIDE];   // tile[c*65 + j], 33.3 KB
    __shared__ int   s_idx[TOK];

    const int tid = threadIdx.x;
    const int b   = blockIdx.y;
    const int t0  = blockIdx.x * TOK;

    if (tid < TOK) s_idx[tid] = idx[(size_t)b * TT + t0 + tid];
    __syncthreads();

    // Gather: 64 tokens x 32 float4 (512B/token, contiguous, L2-resident)
    const float4* WT4 = reinterpret_cast<const float4*>(g_WT);
    #pragma unroll
    for (int it = 0; it < (TOK * 32) / 256; ++it) {   // 8 iters
        int li = it * 256 + tid;
        int j  = li >> 5;                  // token, constant per warp
        int k  = li & 31;                  // lane -> float4 chunk, coalesced
        float4 f = WT4[(size_t)s_idx[j] * 32 + k];
        // channels of chunk k are {k, k+32, k+64, k+96}:
        // store banks = ((k+32m)*65 + j) % 32 = (k + j) % 32 -> conflict-free
        tile[(k     ) * TSTRIDE + j] = f.x;
        tile[(k + 32) * TSTRIDE + j] = f.y;
        tile[(k + 64) * TSTRIDE + j] = f.z;
        tile[(k + 96) * TSTRIDE + j] = f.w;
    }
    __syncthreads();

    // Write: 128 c rows x 16 float4 along t, streamed (bypass L2 persistence)
    float* outb = out + (size_t)b * CC * TT + t0;
    #pragma unroll
    for (int it = 0; it < (CC * (TOK / 4)) / 256; ++it) {   // 8 iters
        int li = it * 256 + tid;
        int c  = li >> 4;                  // 2 c rows per warp
        int t4 = li & 15;
        float4 o;
        // read banks: (c + 4*t4 + m) % 32 -> worst-case 2-way
        o.x = tile[c * TSTRIDE + 4 * t4 + 0];
        o.y = tile[c * TSTRIDE + 4 * t4 + 1];
        o.z = tile[c * TSTRIDE + 4 * t4 + 2];
        o.w = tile[c * TSTRIDE + 4 * t4 + 3];
        __stcs(reinterpret_cast<float4*>(outb + (size_t)c * TT + 4 * t4), o);
    }
}

extern "C" void kernel_launch(void* const* d_in, const int* in_sizes, int n_in,
                              void* d_out, int out_size) {
    const int*   idx  = (const int*)  d_in[0];   // (256,1,2048) int32
    const float* W    = (const float*)d_in[1];   // (128,32000) fp32
    const float* bias = (const float*)d_in[2];   // (128,) fp32
    float*       out  = (float*)      d_out;     // (256,128,2048) fp32

    wt_build_kernel<<<VV / 32, 256>>>(W, bias);
    dim3 grid(TT / TOK, BB);
    gather_kernel<<<grid, 256>>>(idx, out);
}

// round 9
// speedup vs baseline: 1.3115x; 1.3115x over previous
#include <cuda_runtime.h>
#include <cuda_bf16.h>

// out[b,c,t] = W[c, idx[b,t]] + bias[c]
//   idx: (256,1,2048) i32, W: (128,32000) f32, b: (128,) f32
//   out: (256,128,2048) f32 = 256 MB  -> store-bound; floor ~40us.
//
// K1: W -> WT (V x 128) with channel permutation (chunk k = channels
//     {k,k+32,k+64,k+96}) and bias folded in. 16.4 MB, stays L2-resident.
// K2: per block: 256 tokens as 8 tiles of 32, double-buffered smem
//     transpose, software-pipelined: prefetch tile i+1 (LDG.128, L2 hits)
//     overlaps with write of tile i (LDS + STG.128 streamed via __stcs).
//     All smem phases bank-conflict-free.

#define BB  256
#define TT  2048
#define VV  32000
#define CC  128
#define TOK 32          // tokens per tile
#define NT  8           // tiles per block -> 256 tokens/block
#define TSTR 33         // tile row stride (floats), odd -> conflict-free

__device__ float g_WT[(size_t)VV * CC];

// ---------------- K1: transpose + channel-permute + bias fold ----------------
__global__ void __launch_bounds__(256, 6)
wt_build_kernel(const float* __restrict__ W, const float* __restrict__ bias) {
    __shared__ float sm[CC][33];
    const int v0 = blockIdx.x * 32;
    const int tid = threadIdx.x;
    const int vl = tid & 31;
    const int cw = tid >> 5;

    #pragma unroll
    for (int it = 0; it < 16; ++it) {
        int c = it * 8 + cw;
        sm[c][vl] = W[(size_t)c * VV + v0 + vl];
    }
    __syncthreads();

    float4* WT4 = reinterpret_cast<float4*>(g_WT);
    #pragma unroll
    for (int it = 0; it < 4; ++it) {
        int li   = it * 256 + tid;
        int vloc = li >> 5;
        int k    = li & 31;
        float4 f;
        f.x = sm[k     ][vloc] + __ldg(&bias[k     ]);
        f.y = sm[k + 32][vloc] + __ldg(&bias[k + 32]);
        f.z = sm[k + 64][vloc] + __ldg(&bias[k + 64]);
        f.w = sm[k + 96][vloc] + __ldg(&bias[k + 96]);
        WT4[(size_t)(v0 + vloc) * 32 + k] = f;
    }
}

// ---------------- K2: pipelined gather + transpose + streamed store ----------
// grid = (T/(TOK*NT), B) = (8, 256), 256 threads, 6 CTAs/SM target.
__global__ void __launch_bounds__(256, 6)
gather_kernel(const int* __restrict__ idx, float* __restrict__ out) {
    __shared__ float tile[2][CC * TSTR];   // 2 x 16.9 KB
    __shared__ int   s_idx[TOK * NT];      // 256 token ids

    const int tid = threadIdx.x;
    const int b   = blockIdx.y;
    const int t0  = blockIdx.x * (TOK * NT);

    s_idx[tid] = idx[(size_t)b * TT + t0 + tid];
    __syncthreads();

    const float4* __restrict__ WT4 = reinterpret_cast<const float4*>(g_WT);
    const int jg = tid >> 5;          // token within tile (gather phase)
    const int k  = tid & 31;          // float4 chunk = lane -> coalesced LDG

    // Prologue: gather tile 0 into buffer 0.
    {
        float* tb = tile[0];
        #pragma unroll
        for (int it = 0; it < 4; ++it) {
            int j = it * 8 + jg;
            float4 f = WT4[(size_t)s_idx[j] * 32 + k];
            // scatter banks: ((k+32m)*33 + j) % 32 = (k+j) % 32 -> conflict-free
            tb[(k     ) * TSTR + j] = f.x;
            tb[(k + 32) * TSTR + j] = f.y;
            tb[(k + 64) * TSTR + j] = f.z;
            tb[(k + 96) * TSTR + j] = f.w;
        }
    }
    __syncthreads();

    const int c  = tid >> 3;          // write phase: 0..31 (+32*it)
    const int t4 = tid & 7;           // float4 group along t

    #pragma unroll
    for (int i = 0; i < NT; ++i) {
        // Prefetch next tile's rows (L2 hits ~250cyc) - overlapped with write.
        float4 pre[4];
        if (i + 1 < NT) {
            #pragma unroll
            for (int it = 0; it < 4; ++it) {
                int j = (i + 1) * TOK + it * 8 + jg;
                pre[it] = WT4[(size_t)s_idx[j] * 32 + k];
            }
        }

        // Write tile i: coalesced float4 along t, streamed (keep WT in L2).
        {
            const float* tb = tile[i & 1];
            float* outb = out + (size_t)b * CC * TT + t0 + i * TOK;
            #pragma unroll
            for (int it = 0; it < 4; ++it) {
                int cc = it * 32 + c;
                // read banks: (cc + 4*t4 + m) % 32 -> all 32 distinct: conflict-free
                float4 o;
                o.x = tb[cc * TSTR + 4 * t4 + 0];
                o.y = tb[cc * TSTR + 4 * t4 + 1];
                o.z = tb[cc * TSTR + 4 * t4 + 2];
                o.w = tb[cc * TSTR + 4 * t4 + 3];
                __stcs(reinterpret_cast<float4*>(outb + (size_t)cc * TT + 4 * t4), o);
            }
        }

        // Scatter prefetched tile i+1 into the other buffer. Safe without a
        // pre-barrier: all reads of buf[(i+1)&1] (tile i-1) finished before the
        // end-of-iteration barrier of iteration i-1.
        if (i + 1 < NT) {
            float* nb = tile[(i + 1) & 1];
            #pragma unroll
            for (int it = 0; it < 4; ++it) {
                int j = it * 8 + jg;
                nb[(k     ) * TSTR + j] = pre[it].x;
                nb[(k + 32) * TSTR + j] = pre[it].y;
                nb[(k + 64) * TSTR + j] = pre[it].z;
                nb[(k + 96) * TSTR + j] = pre[it].w;
            }
            __syncthreads();
        }
    }
}

extern "C" void kernel_launch(void* const* d_in, const int* in_sizes, int n_in,
                              void* d_out, int out_size) {
    const int*   idx  = (const int*)  d_in[0];
    const float* W    = (const float*)d_in[1];
    const float* bias = (const float*)d_in[2];
    float*       out  = (float*)      d_out;

    wt_build_kernel<<<VV / 32, 256>>>(W, bias);
    dim3 grid(TT / (TOK * NT), BB);
    gather_kernel<<<grid, 256>>>(idx, out);
}